// round 7
// baseline (speedup 1.0000x reference)
#include <cuda_runtime.h>
#include <cstdint>

#define BATCH 16
#define CCH   512
#define NPIX  4096

// attention / energy scratch: 16 MB
__device__ float g_energy[(size_t)BATCH * CCH * CCH];

// ---------------------------------------------------------------------------
// helpers
// ---------------------------------------------------------------------------
__device__ __forceinline__ uint32_t hi_tf32(float x) {
    return __float_as_uint(x) & 0xFFFFE000u;   // exact tf32 (top 19 bits)
}
__device__ __forceinline__ uint32_t lo_tf32(float x, uint32_t hibits) {
    float lo = x - __uint_as_float(hibits);
    uint32_t r;
    asm("cvt.rna.tf32.f32 %0, %1;" : "=r"(r) : "f"(lo));
    return r;
}
__device__ __forceinline__ uint32_t rna_tf32(float x) {
    uint32_t r;
    asm("cvt.rna.tf32.f32 %0, %1;" : "=r"(r) : "f"(x));
    return r;
}
// NOTE: a/b fragments use a permuted physical-k ordering (thread qp supplies
// physical k {2qp, 2qp+1} instead of {qp, qp+4}). The mma sums over all 8 k;
// any bijection is valid as long as A and B agree — this makes frag loads
// 8-byte contiguous (LDS.64).
__device__ __forceinline__ void mma8(float* d, const uint32_t* a, const uint32_t* b) {
    asm volatile(
        "mma.sync.aligned.m16n8k8.row.col.f32.tf32.tf32.f32 "
        "{%0,%1,%2,%3}, {%4,%5,%6,%7}, {%8,%9}, {%0,%1,%2,%3};"
        : "+f"(d[0]), "+f"(d[1]), "+f"(d[2]), "+f"(d[3])
        : "r"(a[0]), "r"(a[1]), "r"(a[2]), "r"(a[3]), "r"(b[0]), "r"(b[1]));
}
__device__ __forceinline__ void split_store(uint32_t* dH, uint32_t* dL, float4 v) {
    uint4 h, l;
    h.x = hi_tf32(v.x); h.y = hi_tf32(v.y); h.z = hi_tf32(v.z); h.w = hi_tf32(v.w);
    l.x = lo_tf32(v.x, h.x); l.y = lo_tf32(v.y, h.y);
    l.z = lo_tf32(v.z, h.z); l.w = lo_tf32(v.w, h.w);
    *(uint4*)dH = h;
    *(uint4*)dL = l;
}
__device__ __forceinline__ void rna_store(uint32_t* d, float4 v) {
    uint4 h;
    h.x = rna_tf32(v.x); h.y = rna_tf32(v.y); h.z = rna_tf32(v.z); h.w = rna_tf32(v.w);
    *(uint4*)d = h;
}

#define RS 36                 // m-major row stride (floats)

// ---------------------------------------------------------------------------
// Kernel 1: energy[b] = q qᵀ  (3xTF32, symmetric: 36 upper 64x64 blocks)
// 128 thr (4 warps 2x2, warp tile 32x32), BK=32, double-buffered hi/lo smem.
// ---------------------------------------------------------------------------
#define ET64   (64 * RS)                  // 2304 u32 per 64x32 tile
#define ESTAGE (4 * ET64)                 // AH|AL|BH|BL = 9216 u32
#define ESMEM_BYTES (2 * ESTAGE * 4)      // 73728

__global__ __launch_bounds__(128) void energy_kernel(const float* __restrict__ x)
{
    extern __shared__ uint32_t sm[];
    const int tid = threadIdx.x, lane = tid & 31, wid = tid >> 5;
    const int b = blockIdx.y;

    // upper-triangle pair (bi <= bj) of 64-blocks from blockIdx.x in [0,36)
    int bi = 0, t = blockIdx.x, rowlen = 8;
    while (t >= rowlen) { t -= rowlen; bi++; rowlen--; }
    const int bj = bi + t;

    const float* q = x + (size_t)b * CCH * NPIX;
    const int m0 = bi * 64, n0 = bj * 64;

    const int wm = (wid >> 1) * 32, wn = (wid & 1) * 32;
    const int qm = lane >> 2, qp = lane & 3;
    const int q2 = 2 * qp;

    int rr[4], cc[4];
#pragma unroll
    for (int i = 0; i < 4; i++) { int idx = tid + 128 * i; rr[i] = idx >> 3; cc[i] = (idx & 7) * 4; }

    float acc[2][4][4];
#pragma unroll
    for (int i = 0; i < 2; i++)
#pragma unroll
        for (int j = 0; j < 4; j++)
#pragma unroll
            for (int k = 0; k < 4; k++) acc[i][j][k] = 0.f;

    float4 ra[4], rb[4];
#pragma unroll
    for (int i = 0; i < 4; i++) {
        ra[i] = *(const float4*)(q + (size_t)(m0 + rr[i]) * NPIX + cc[i]);
        rb[i] = *(const float4*)(q + (size_t)(n0 + rr[i]) * NPIX + cc[i]);
    }
#pragma unroll
    for (int i = 0; i < 4; i++) {
        int off = rr[i] * RS + cc[i];
        split_store(sm + off,            sm + ET64 + off,     ra[i]);
        split_store(sm + 2 * ET64 + off, sm + 3 * ET64 + off, rb[i]);
    }
    __syncthreads();

    int s = 0;
    constexpr int NCH = NPIX / 32;   // 128
    for (int it = 0; it < NCH; ++it) {
        if (it + 1 < NCH) {
            const int k0 = (it + 1) * 32;
#pragma unroll
            for (int i = 0; i < 4; i++) {
                ra[i] = *(const float4*)(q + (size_t)(m0 + rr[i]) * NPIX + k0 + cc[i]);
                rb[i] = *(const float4*)(q + (size_t)(n0 + rr[i]) * NPIX + k0 + cc[i]);
            }
        }
        {
            const uint32_t* AH = sm + s * ESTAGE;
            const uint32_t* AL = AH + ET64;
            const uint32_t* BH = AH + 2 * ET64;
            const uint32_t* BL = AH + 3 * ET64;
#pragma unroll
            for (int kk = 0; kk < 32; kk += 8) {
                uint32_t ah[2][4], al[2][4], bh[4][2], bl[4][2];
#pragma unroll
                for (int j = 0; j < 4; j++) {
                    const int ro = (wn + j * 8 + qm) * RS + kk + q2;
                    uint2 h = *(const uint2*)(BH + ro);
                    uint2 l = *(const uint2*)(BL + ro);
                    bh[j][0] = h.x; bh[j][1] = h.y;
                    bl[j][0] = l.x; bl[j][1] = l.y;
                }
#pragma unroll
                for (int i = 0; i < 2; i++) {
                    const int ro = (wm + i * 16 + qm) * RS + kk + q2;
                    uint2 h0 = *(const uint2*)(AH + ro);
                    uint2 h1 = *(const uint2*)(AH + ro + 8 * RS);
                    uint2 l0 = *(const uint2*)(AL + ro);
                    uint2 l1 = *(const uint2*)(AL + ro + 8 * RS);
                    ah[i][0] = h0.x; ah[i][2] = h0.y; ah[i][1] = h1.x; ah[i][3] = h1.y;
                    al[i][0] = l0.x; al[i][2] = l0.y; al[i][1] = l1.x; al[i][3] = l1.y;
                }
#pragma unroll
                for (int i = 0; i < 2; i++)
#pragma unroll
                    for (int j = 0; j < 4; j++) mma8(acc[i][j], ah[i], bh[j]);
#pragma unroll
                for (int i = 0; i < 2; i++)
#pragma unroll
                    for (int j = 0; j < 4; j++) mma8(acc[i][j], ah[i], bl[j]);
#pragma unroll
                for (int i = 0; i < 2; i++)
#pragma unroll
                    for (int j = 0; j < 4; j++) mma8(acc[i][j], al[i], bh[j]);
            }
        }
        if (it + 1 < NCH) {
            __syncthreads();
            uint32_t* S = sm + (s ^ 1) * ESTAGE;
#pragma unroll
            for (int i = 0; i < 4; i++) {
                int off = rr[i] * RS + cc[i];
                split_store(S + off,            S + ET64 + off,     ra[i]);
                split_store(S + 2 * ET64 + off, S + 3 * ET64 + off, rb[i]);
            }
            __syncthreads();
            s ^= 1;
        }
    }

    float* E = g_energy + (size_t)b * CCH * CCH;
    const bool mir = (bi != bj);
#pragma unroll
    for (int i = 0; i < 2; i++)
#pragma unroll
        for (int j = 0; j < 4; j++) {
            const int m = m0 + wm + i * 16 + qm;
            const int n = n0 + wn + j * 8 + qp * 2;
            float2 v0 = make_float2(acc[i][j][0], acc[i][j][1]);
            float2 v1 = make_float2(acc[i][j][2], acc[i][j][3]);
            *(float2*)&E[(size_t)m * CCH + n]       = v0;
            *(float2*)&E[(size_t)(m + 8) * CCH + n] = v1;
            if (mir) {
                E[(size_t)n * CCH + m]           = v0.x;
                E[(size_t)(n + 1) * CCH + m]     = v0.y;
                E[(size_t)n * CCH + m + 8]       = v1.x;
                E[(size_t)(n + 1) * CCH + m + 8] = v1.y;
            }
        }
}

// ---------------------------------------------------------------------------
// Kernel 2: in-place row softmax of exp(rowmin - e)/sum  (== softmax(max - e))
// ---------------------------------------------------------------------------
__global__ __launch_bounds__(256) void softmax_kernel()
{
    const int row  = blockIdx.x * 8 + (threadIdx.x >> 5);
    const int lane = threadIdx.x & 31;
    float* e = g_energy + (size_t)row * CCH;

    float v[16];
    float mn = 3.4e38f;
#pragma unroll
    for (int i = 0; i < 16; i++) { v[i] = e[lane + i * 32]; mn = fminf(mn, v[i]); }
#pragma unroll
    for (int o = 16; o > 0; o >>= 1)
        mn = fminf(mn, __shfl_xor_sync(0xffffffffu, mn, o));
    float s = 0.f;
#pragma unroll
    for (int i = 0; i < 16; i++) { v[i] = expf(mn - v[i]); s += v[i]; }
#pragma unroll
    for (int o = 16; o > 0; o >>= 1)
        s += __shfl_xor_sync(0xffffffffu, s, o);
    const float r = 1.0f / s;
#pragma unroll
    for (int i = 0; i < 16; i++) e[lane + i * 32] = v[i] * r;
}

// ---------------------------------------------------------------------------
// Kernel 3: y[b] = gamma * (attn[b] @ q[b]) + x[b]   (1-pass rna TF32)
// A = attn rna [128,32] m-major RS=36; B = q rna [32,128] k-major BRS=132.
// 512 thr, warps 4x4, warp tile 32x32.
// ---------------------------------------------------------------------------
#define ET (128 * RS)                         // 4608 u32
#define BRS 132
#define OT_B (32 * BRS)                       // 4224 u32
#define OSTAGE (ET + OT_B)                    // 8832 u32
#define OSMEM_BYTES (2 * OSTAGE * 4)          // 70656

__global__ __launch_bounds__(512) void out_kernel(const float* __restrict__ x,
                                                  const float* __restrict__ gamma,
                                                  float* __restrict__ out)
{
    extern __shared__ uint32_t sm[];
    const int tid = threadIdx.x, lane = tid & 31, wid = tid >> 5;
    const int b = blockIdx.z;
    const float* A = g_energy + (size_t)b * CCH * CCH;
    const float* q = x + (size_t)b * CCH * NPIX;
    const int m0 = blockIdx.y * 128;
    const int n0 = blockIdx.x * 128;

    const int wm = (wid >> 2) * 32, wn = (wid & 3) * 32;
    const int qm = lane >> 2, qp = lane & 3;
    const int q2 = 2 * qp;

    int ar[2], ac[2], bk[2], bn[2];
#pragma unroll
    for (int i = 0; i < 2; i++) {
        int idx = tid + 512 * i;
        ar[i] = idx >> 3;  ac[i] = (idx & 7) * 4;    // A tile 128x32
        bk[i] = idx >> 5;  bn[i] = (idx & 31) * 4;   // B tile 32x128
    }

    float acc[2][4][4];
#pragma unroll
    for (int i = 0; i < 2; i++)
#pragma unroll
        for (int j = 0; j < 4; j++)
#pragma unroll
            for (int k = 0; k < 4; k++) acc[i][j][k] = 0.f;

    float4 ra[2], rb[2];
#pragma unroll
    for (int i = 0; i < 2; i++) {
        ra[i] = *(const float4*)(A + (size_t)(m0 + ar[i]) * CCH + ac[i]);
        rb[i] = *(const float4*)(q + (size_t)bk[i] * NPIX + n0 + bn[i]);
    }
#pragma unroll
    for (int i = 0; i < 2; i++) {
        rna_store(sm + ar[i] * RS + ac[i], ra[i]);
        rna_store(sm + ET + bk[i] * BRS + bn[i], rb[i]);
    }
    __syncthreads();

    int s = 0;
    constexpr int NCH = CCH / 32;   // 16
    for (int it = 0; it < NCH; ++it) {
        if (it + 1 < NCH) {
            const int k0 = (it + 1) * 32;
#pragma unroll
            for (int i = 0; i < 2; i++) {
                ra[i] = *(const float4*)(A + (size_t)(m0 + ar[i]) * CCH + k0 + ac[i]);
                rb[i] = *(const float4*)(q + (size_t)(k0 + bk[i]) * NPIX + n0 + bn[i]);
            }
        }
        {
            const uint32_t* AH = sm + s * OSTAGE;
            const uint32_t* BH = AH + ET;
#pragma unroll
            for (int kk = 0; kk < 32; kk += 8) {
                uint32_t ah[2][4], bh[4][2];
#pragma unroll
                for (int j = 0; j < 4; j++) {
                    const int co = wn + j * 8 + qm;
                    bh[j][0] = BH[(kk + q2) * BRS + co];
                    bh[j][1] = BH[(kk + q2 + 1) * BRS + co];
                }
#pragma unroll
                for (int i = 0; i < 2; i++) {
                    const int ro = (wm + i * 16 + qm) * RS + kk + q2;
                    uint2 h0 = *(const uint2*)(AH + ro);
                    uint2 h1 = *(const uint2*)(AH + ro + 8 * RS);
                    ah[i][0] = h0.x; ah[i][2] = h0.y; ah[i][1] = h1.x; ah[i][3] = h1.y;
                }
#pragma unroll
                for (int i = 0; i < 2; i++)
#pragma unroll
                    for (int j = 0; j < 4; j++) mma8(acc[i][j], ah[i], bh[j]);
            }
        }
        if (it + 1 < NCH) {
            __syncthreads();
            uint32_t* S = sm + (s ^ 1) * OSTAGE;
#pragma unroll
            for (int i = 0; i < 2; i++) {
                rna_store(S + ar[i] * RS + ac[i], ra[i]);
                rna_store(S + ET + bk[i] * BRS + bn[i], rb[i]);
            }
            __syncthreads();
            s ^= 1;
        }
    }

    const float g = *gamma;
#pragma unroll
    for (int i = 0; i < 2; i++)
#pragma unroll
        for (int j = 0; j < 4; j++) {
            const int m = m0 + wm + i * 16 + qm;
            const int n = n0 + wn + j * 8 + qp * 2;
            {
                const size_t p = (size_t)(b * CCH + m) * NPIX + n;
                float2 xv = *(const float2*)(x + p);
                float2 o;
                o.x = fmaf(g, acc[i][j][0], xv.x);
                o.y = fmaf(g, acc[i][j][1], xv.y);
                *(float2*)(out + p) = o;
            }
            {
                const size_t p = (size_t)(b * CCH + m + 8) * NPIX + n;
                float2 xv = *(const float2*)(x + p);
                float2 o;
                o.x = fmaf(g, acc[i][j][2], xv.x);
                o.y = fmaf(g, acc[i][j][3], xv.y);
                *(float2*)(out + p) = o;
            }
        }
}

// ---------------------------------------------------------------------------
extern "C" void kernel_launch(void* const* d_in, const int* in_sizes, int n_in,
                              void* d_out, int out_size)
{
    const float* x     = (const float*)d_in[0];
    const float* gamma = (const float*)d_in[1];
    float* out = (float*)d_out;

    cudaFuncSetAttribute(energy_kernel,
                         cudaFuncAttributeMaxDynamicSharedMemorySize, ESMEM_BYTES);
    cudaFuncSetAttribute(out_kernel,
                         cudaFuncAttributeMaxDynamicSharedMemorySize, OSMEM_BYTES);

    energy_kernel<<<dim3(36, BATCH), 128, ESMEM_BYTES>>>(x);
    softmax_kernel<<<(BATCH * CCH) / 8, 256>>>();
    out_kernel<<<dim3(NPIX / 128, CCH / 128, BATCH), 512, OSMEM_BYTES>>>(x, gamma, out);
}

// round 8
// speedup vs baseline: 1.1545x; 1.1545x over previous
#include <cuda_runtime.h>
#include <cstdint>

#define BATCH 16
#define CCH   512
#define NPIX  4096

// attention / energy scratch: 16 MB
__device__ float g_energy[(size_t)BATCH * CCH * CCH];

// ---------------------------------------------------------------------------
// helpers
// ---------------------------------------------------------------------------
__device__ __forceinline__ uint32_t hi_tf32(float x) {
    return __float_as_uint(x) & 0xFFFFE000u;   // exact tf32 (top 19 bits)
}
__device__ __forceinline__ uint32_t lo_tf32(float x, uint32_t hibits) {
    float lo = x - __uint_as_float(hibits);
    uint32_t r;
    asm("cvt.rna.tf32.f32 %0, %1;" : "=r"(r) : "f"(lo));
    return r;
}
__device__ __forceinline__ uint32_t rna_tf32(float x) {
    uint32_t r;
    asm("cvt.rna.tf32.f32 %0, %1;" : "=r"(r) : "f"(x));
    return r;
}
// a/b fragments use a permuted physical-k ordering (thread qp supplies
// physical k {2qp, 2qp+1}); valid since A and B agree on the permutation.
__device__ __forceinline__ void mma8(float* d, const uint32_t* a, const uint32_t* b) {
    asm volatile(
        "mma.sync.aligned.m16n8k8.row.col.f32.tf32.tf32.f32 "
        "{%0,%1,%2,%3}, {%4,%5,%6,%7}, {%8,%9}, {%0,%1,%2,%3};"
        : "+f"(d[0]), "+f"(d[1]), "+f"(d[2]), "+f"(d[3])
        : "r"(a[0]), "r"(a[1]), "r"(a[2]), "r"(a[3]), "r"(b[0]), "r"(b[1]));
}
__device__ __forceinline__ void split_store(uint32_t* dH, uint32_t* dL, float4 v) {
    uint4 h, l;
    h.x = hi_tf32(v.x); h.y = hi_tf32(v.y); h.z = hi_tf32(v.z); h.w = hi_tf32(v.w);
    l.x = lo_tf32(v.x, h.x); l.y = lo_tf32(v.y, h.y);
    l.z = lo_tf32(v.z, h.z); l.w = lo_tf32(v.w, h.w);
    *(uint4*)dH = h;
    *(uint4*)dL = l;
}
__device__ __forceinline__ void rna_store(uint32_t* d, float4 v) {
    uint4 h;
    h.x = rna_tf32(v.x); h.y = rna_tf32(v.y); h.z = rna_tf32(v.z); h.w = rna_tf32(v.w);
    *(uint4*)d = h;
}

// RS=40: for 64-bit LDS at word addr row*40 + 2*qp, bank-pair index is
// (row*20 + qp) mod 16 = (4*row + qp) mod 16 -> conflict-free per half-warp.
#define RS 40

// ---------------------------------------------------------------------------
// Kernel 1: energy[b] = q qᵀ  (3xTF32, symmetric: 36 upper 64x64 blocks)
// 128 thr (4 warps 2x2, warp tile 32x32), BK=32, double-buffered hi/lo smem.
// ---------------------------------------------------------------------------
#define ET64   (64 * RS)                  // 2560 u32 per 64x32 tile
#define ESTAGE (4 * ET64)                 // AH|AL|BH|BL = 10240 u32
#define ESMEM_BYTES (2 * ESTAGE * 4)      // 81920

__global__ __launch_bounds__(128) void energy_kernel(const float* __restrict__ x)
{
    extern __shared__ uint32_t sm[];
    const int tid = threadIdx.x, lane = tid & 31, wid = tid >> 5;
    const int b = blockIdx.y;

    // upper-triangle pair (bi <= bj) of 64-blocks from blockIdx.x in [0,36)
    int bi = 0, t = blockIdx.x, rowlen = 8;
    while (t >= rowlen) { t -= rowlen; bi++; rowlen--; }
    const int bj = bi + t;

    const float* q = x + (size_t)b * CCH * NPIX;
    const int m0 = bi * 64, n0 = bj * 64;

    const int wm = (wid >> 1) * 32, wn = (wid & 1) * 32;
    const int qm = lane >> 2, qp = lane & 3;
    const int q2 = 2 * qp;

    int rr[4], cc[4];
#pragma unroll
    for (int i = 0; i < 4; i++) { int idx = tid + 128 * i; rr[i] = idx >> 3; cc[i] = (idx & 7) * 4; }

    float acc[2][4][4];
#pragma unroll
    for (int i = 0; i < 2; i++)
#pragma unroll
        for (int j = 0; j < 4; j++)
#pragma unroll
            for (int k = 0; k < 4; k++) acc[i][j][k] = 0.f;

    float4 ra[4], rb[4];
#pragma unroll
    for (int i = 0; i < 4; i++) {
        ra[i] = *(const float4*)(q + (size_t)(m0 + rr[i]) * NPIX + cc[i]);
        rb[i] = *(const float4*)(q + (size_t)(n0 + rr[i]) * NPIX + cc[i]);
    }
#pragma unroll
    for (int i = 0; i < 4; i++) {
        int off = rr[i] * RS + cc[i];
        split_store(sm + off,            sm + ET64 + off,     ra[i]);
        split_store(sm + 2 * ET64 + off, sm + 3 * ET64 + off, rb[i]);
    }
    __syncthreads();

    int s = 0;
    constexpr int NCH = NPIX / 32;   // 128
    for (int it = 0; it < NCH; ++it) {
        if (it + 1 < NCH) {
            const int k0 = (it + 1) * 32;
#pragma unroll
            for (int i = 0; i < 4; i++) {
                ra[i] = *(const float4*)(q + (size_t)(m0 + rr[i]) * NPIX + k0 + cc[i]);
                rb[i] = *(const float4*)(q + (size_t)(n0 + rr[i]) * NPIX + k0 + cc[i]);
            }
        }
        {
            const uint32_t* AH = sm + s * ESTAGE;
            const uint32_t* AL = AH + ET64;
            const uint32_t* BH = AH + 2 * ET64;
            const uint32_t* BL = AH + 3 * ET64;
#pragma unroll
            for (int kk = 0; kk < 32; kk += 8) {
                uint32_t ah[2][4], al[2][4], bh[4][2], bl[4][2];
#pragma unroll
                for (int j = 0; j < 4; j++) {
                    const int ro = (wn + j * 8 + qm) * RS + kk + q2;
                    uint2 h = *(const uint2*)(BH + ro);
                    uint2 l = *(const uint2*)(BL + ro);
                    bh[j][0] = h.x; bh[j][1] = h.y;
                    bl[j][0] = l.x; bl[j][1] = l.y;
                }
#pragma unroll
                for (int i = 0; i < 2; i++) {
                    const int ro = (wm + i * 16 + qm) * RS + kk + q2;
                    uint2 h0 = *(const uint2*)(AH + ro);
                    uint2 h1 = *(const uint2*)(AH + ro + 8 * RS);
                    uint2 l0 = *(const uint2*)(AL + ro);
                    uint2 l1 = *(const uint2*)(AL + ro + 8 * RS);
                    ah[i][0] = h0.x; ah[i][2] = h0.y; ah[i][1] = h1.x; ah[i][3] = h1.y;
                    al[i][0] = l0.x; al[i][2] = l0.y; al[i][1] = l1.x; al[i][3] = l1.y;
                }
#pragma unroll
                for (int i = 0; i < 2; i++)
#pragma unroll
                    for (int j = 0; j < 4; j++) mma8(acc[i][j], ah[i], bh[j]);
#pragma unroll
                for (int i = 0; i < 2; i++)
#pragma unroll
                    for (int j = 0; j < 4; j++) mma8(acc[i][j], ah[i], bl[j]);
#pragma unroll
                for (int i = 0; i < 2; i++)
#pragma unroll
                    for (int j = 0; j < 4; j++) mma8(acc[i][j], al[i], bh[j]);
            }
        }
        if (it + 1 < NCH) {
            __syncthreads();
            uint32_t* S = sm + (s ^ 1) * ESTAGE;
#pragma unroll
            for (int i = 0; i < 4; i++) {
                int off = rr[i] * RS + cc[i];
                split_store(S + off,            S + ET64 + off,     ra[i]);
                split_store(S + 2 * ET64 + off, S + 3 * ET64 + off, rb[i]);
            }
            __syncthreads();
            s ^= 1;
        }
    }

    float* E = g_energy + (size_t)b * CCH * CCH;
    const bool mir = (bi != bj);
#pragma unroll
    for (int i = 0; i < 2; i++)
#pragma unroll
        for (int j = 0; j < 4; j++) {
            const int m = m0 + wm + i * 16 + qm;
            const int n = n0 + wn + j * 8 + qp * 2;
            float2 v0 = make_float2(acc[i][j][0], acc[i][j][1]);
            float2 v1 = make_float2(acc[i][j][2], acc[i][j][3]);
            *(float2*)&E[(size_t)m * CCH + n]       = v0;
            *(float2*)&E[(size_t)(m + 8) * CCH + n] = v1;
            if (mir) {
                E[(size_t)n * CCH + m]           = v0.x;
                E[(size_t)(n + 1) * CCH + m]     = v0.y;
                E[(size_t)n * CCH + m + 8]       = v1.x;
                E[(size_t)(n + 1) * CCH + m + 8] = v1.y;
            }
        }
}

// ---------------------------------------------------------------------------
// Kernel 2: in-place row softmax of exp(rowmin - e)/sum  (== softmax(max - e))
// ---------------------------------------------------------------------------
__global__ __launch_bounds__(256) void softmax_kernel()
{
    const int row  = blockIdx.x * 8 + (threadIdx.x >> 5);
    const int lane = threadIdx.x & 31;
    float* e = g_energy + (size_t)row * CCH;

    float v[16];
    float mn = 3.4e38f;
#pragma unroll
    for (int i = 0; i < 16; i++) { v[i] = e[lane + i * 32]; mn = fminf(mn, v[i]); }
#pragma unroll
    for (int o = 16; o > 0; o >>= 1)
        mn = fminf(mn, __shfl_xor_sync(0xffffffffu, mn, o));
    float s = 0.f;
#pragma unroll
    for (int i = 0; i < 16; i++) { v[i] = expf(mn - v[i]); s += v[i]; }
#pragma unroll
    for (int o = 16; o > 0; o >>= 1)
        s += __shfl_xor_sync(0xffffffffu, s, o);
    const float r = 1.0f / s;
#pragma unroll
    for (int i = 0; i < 16; i++) e[lane + i * 32] = v[i] * r;
}

// ---------------------------------------------------------------------------
// Kernel 3: y[b] = gamma * (attn[b] @ q[b]) + x[b]   (1-pass rna TF32)
// A = attn rna [128,32] m-major RS=40; B = q rna [32,128] k-major BRS=132.
// 512 thr, warps 4x4, warp tile 32x32.
// ---------------------------------------------------------------------------
#define ET (128 * RS)                         // 5120 u32
#define BRS 132
#define OT_B (32 * BRS)                       // 4224 u32
#define OSTAGE (ET + OT_B)                    // 9344 u32
#define OSMEM_BYTES (2 * OSTAGE * 4)          // 74752

__global__ __launch_bounds__(512) void out_kernel(const float* __restrict__ x,
                                                  const float* __restrict__ gamma,
                                                  float* __restrict__ out)
{
    extern __shared__ uint32_t sm[];
    const int tid = threadIdx.x, lane = tid & 31, wid = tid >> 5;
    const int b = blockIdx.z;
    const float* A = g_energy + (size_t)b * CCH * CCH;
    const float* q = x + (size_t)b * CCH * NPIX;
    const int m0 = blockIdx.y * 128;
    const int n0 = blockIdx.x * 128;

    const int wm = (wid >> 2) * 32, wn = (wid & 3) * 32;
    const int qm = lane >> 2, qp = lane & 3;
    const int q2 = 2 * qp;

    int ar[2], ac[2], bk[2], bn[2];
#pragma unroll
    for (int i = 0; i < 2; i++) {
        int idx = tid + 512 * i;
        ar[i] = idx >> 3;  ac[i] = (idx & 7) * 4;    // A tile 128x32
        bk[i] = idx >> 5;  bn[i] = (idx & 31) * 4;   // B tile 32x128
    }

    float acc[2][4][4];
#pragma unroll
    for (int i = 0; i < 2; i++)
#pragma unroll
        for (int j = 0; j < 4; j++)
#pragma unroll
            for (int k = 0; k < 4; k++) acc[i][j][k] = 0.f;

    float4 ra[2], rb[2];
#pragma unroll
    for (int i = 0; i < 2; i++) {
        ra[i] = *(const float4*)(A + (size_t)(m0 + ar[i]) * CCH + ac[i]);
        rb[i] = *(const float4*)(q + (size_t)bk[i] * NPIX + n0 + bn[i]);
    }
#pragma unroll
    for (int i = 0; i < 2; i++) {
        rna_store(sm + ar[i] * RS + ac[i], ra[i]);
        rna_store(sm + ET + bk[i] * BRS + bn[i], rb[i]);
    }
    __syncthreads();

    int s = 0;
    constexpr int NCH = CCH / 32;   // 16
    for (int it = 0; it < NCH; ++it) {
        if (it + 1 < NCH) {
            const int k0 = (it + 1) * 32;
#pragma unroll
            for (int i = 0; i < 2; i++) {
                ra[i] = *(const float4*)(A + (size_t)(m0 + ar[i]) * CCH + k0 + ac[i]);
                rb[i] = *(const float4*)(q + (size_t)(k0 + bk[i]) * NPIX + n0 + bn[i]);
            }
        }
        {
            const uint32_t* AH = sm + s * OSTAGE;
            const uint32_t* BH = AH + ET;
#pragma unroll
            for (int kk = 0; kk < 32; kk += 8) {
                uint32_t ah[2][4], bh[4][2];
#pragma unroll
                for (int j = 0; j < 4; j++) {
                    const int co = wn + j * 8 + qm;
                    bh[j][0] = BH[(kk + q2) * BRS + co];
                    bh[j][1] = BH[(kk + q2 + 1) * BRS + co];
                }
#pragma unroll
                for (int i = 0; i < 2; i++) {
                    const int ro = (wm + i * 16 + qm) * RS + kk + q2;
                    uint2 h0 = *(const uint2*)(AH + ro);
                    uint2 h1 = *(const uint2*)(AH + ro + 8 * RS);
                    ah[i][0] = h0.x; ah[i][2] = h0.y; ah[i][1] = h1.x; ah[i][3] = h1.y;
                }
#pragma unroll
                for (int i = 0; i < 2; i++)
#pragma unroll
                    for (int j = 0; j < 4; j++) mma8(acc[i][j], ah[i], bh[j]);
            }
        }
        if (it + 1 < NCH) {
            __syncthreads();
            uint32_t* S = sm + (s ^ 1) * OSTAGE;
#pragma unroll
            for (int i = 0; i < 2; i++) {
                rna_store(S + ar[i] * RS + ac[i], ra[i]);
                rna_store(S + ET + bk[i] * BRS + bn[i], rb[i]);
            }
            __syncthreads();
            s ^= 1;
        }
    }

    const float g = *gamma;
#pragma unroll
    for (int i = 0; i < 2; i++)
#pragma unroll
        for (int j = 0; j < 4; j++) {
            const int m = m0 + wm + i * 16 + qm;
            const int n = n0 + wn + j * 8 + qp * 2;
            {
                const size_t p = (size_t)(b * CCH + m) * NPIX + n;
                float2 xv = *(const float2*)(x + p);
                float2 o;
                o.x = fmaf(g, acc[i][j][0], xv.x);
                o.y = fmaf(g, acc[i][j][1], xv.y);
                *(float2*)(out + p) = o;
            }
            {
                const size_t p = (size_t)(b * CCH + m + 8) * NPIX + n;
                float2 xv = *(const float2*)(x + p);
                float2 o;
                o.x = fmaf(g, acc[i][j][2], xv.x);
                o.y = fmaf(g, acc[i][j][3], xv.y);
                *(float2*)(out + p) = o;
            }
        }
}

// ---------------------------------------------------------------------------
extern "C" void kernel_launch(void* const* d_in, const int* in_sizes, int n_in,
                              void* d_out, int out_size)
{
    const float* x     = (const float*)d_in[0];
    const float* gamma = (const float*)d_in[1];
    float* out = (float*)d_out;

    cudaFuncSetAttribute(energy_kernel,
                         cudaFuncAttributeMaxDynamicSharedMemorySize, ESMEM_BYTES);
    cudaFuncSetAttribute(out_kernel,
                         cudaFuncAttributeMaxDynamicSharedMemorySize, OSMEM_BYTES);

    energy_kernel<<<dim3(36, BATCH), 128, ESMEM_BYTES>>>(x);
    softmax_kernel<<<(BATCH * CCH) / 8, 256>>>();
    out_kernel<<<dim3(NPIX / 128, CCH / 128, BATCH), 512, OSMEM_BYTES>>>(x, gamma, out);
}

// round 10
// speedup vs baseline: 2.1218x; 1.8379x over previous
#include <cuda_runtime.h>
#include <cuda_fp16.h>
#include <cstdint>

#define BATCH 16
#define CCH   512
#define NPIX  4096
#define NTOT  ((size_t)BATCH * CCH * NPIX)

// scratch
__device__ float  g_energy[(size_t)BATCH * CCH * CCH];   // 16 MB fp32 energy
__device__ __half g_attn  [(size_t)BATCH * CCH * CCH];   // 8 MB fp16 attention
__device__ __half g_qh[NTOT];                            // 64 MB: rn(q)
__device__ __half g_ql[NTOT];                            // 64 MB: rn(q - qh)

// ---------------------------------------------------------------------------
// PTX helpers (all base-ISA: sm_75/80 ops, legal under compute_103)
// ---------------------------------------------------------------------------
__device__ __forceinline__ uint32_t smem_u32(const void* p) {
    uint32_t a;
    asm("{ .reg .u64 t; cvta.to.shared.u64 t, %1; cvt.u32.u64 %0, t; }" : "=r"(a) : "l"(p));
    return a;
}
__device__ __forceinline__ void ldm_x4(uint32_t* r, uint32_t addr) {
    asm volatile("ldmatrix.sync.aligned.m8n8.x4.shared.b16 {%0,%1,%2,%3}, [%4];"
        : "=r"(r[0]), "=r"(r[1]), "=r"(r[2]), "=r"(r[3]) : "r"(addr));
}
__device__ __forceinline__ void ldm_x4_t(uint32_t* r, uint32_t addr) {
    asm volatile("ldmatrix.sync.aligned.m8n8.x4.trans.shared.b16 {%0,%1,%2,%3}, [%4];"
        : "=r"(r[0]), "=r"(r[1]), "=r"(r[2]), "=r"(r[3]) : "r"(addr));
}
__device__ __forceinline__ void mma16(float* d, const uint32_t* a, const uint32_t* b) {
    asm volatile(
        "mma.sync.aligned.m16n8k16.row.col.f32.f16.f16.f32 "
        "{%0,%1,%2,%3}, {%4,%5,%6,%7}, {%8,%9}, {%0,%1,%2,%3};"
        : "+f"(d[0]), "+f"(d[1]), "+f"(d[2]), "+f"(d[3])
        : "r"(a[0]), "r"(a[1]), "r"(a[2]), "r"(a[3]), "r"(b[0]), "r"(b[1]));
}
__device__ __forceinline__ void cp16(uint32_t saddr, const void* g) {
    asm volatile("cp.async.cg.shared.global [%0], [%1], 16;" :: "r"(saddr), "l"(g) : "memory");
}
#define CP_COMMIT() asm volatile("cp.async.commit_group;" ::: "memory")
#define CP_WAIT(n)  asm volatile("cp.async.wait_group %0;" :: "n"(n) : "memory")

// ---------------------------------------------------------------------------
// Kernel 0: split q -> qh (rn fp16) + ql (rn residual fp16)
// ---------------------------------------------------------------------------
__global__ __launch_bounds__(256) void split_kernel(const float* __restrict__ x)
{
    size_t i = ((size_t)blockIdx.x * 256 + threadIdx.x) * 4;
    float4 v = *(const float4*)(x + i);
    __half2 h0 = __floats2half2_rn(v.x, v.y);
    __half2 h1 = __floats2half2_rn(v.z, v.w);
    float2 f0 = __half22float2(h0), f1 = __half22float2(h1);
    __half2 l0 = __floats2half2_rn(v.x - f0.x, v.y - f0.y);
    __half2 l1 = __floats2half2_rn(v.z - f1.x, v.w - f1.y);
    *(uint2*)(g_qh + i) = make_uint2(*(uint32_t*)&h0, *(uint32_t*)&h1);
    *(uint2*)(g_ql + i) = make_uint2(*(uint32_t*)&l0, *(uint32_t*)&l1);
}

// ---------------------------------------------------------------------------
// Kernel 1: energy[b] = q qᵀ (3-pass fp16: hh + hl + lh), symmetric 64x64 blocks.
// 128 thr (4 warps 2x2, warp 32x32), BK=32, cp.async double-buffer, ldmatrix.
// Tiles: 64 rows x 32 fp16, row stride 40 fp16 (80 B -> ldmatrix conflict-free).
// ---------------------------------------------------------------------------
#define ERS_B  80                       // row stride bytes
#define ETILE_B (64 * ERS_B)            // 5120 B per tile
#define ESTAGE_B (4 * ETILE_B)          // AH|AL|BH|BL = 20480 B

__global__ __launch_bounds__(128) void energy_kernel()
{
    __shared__ __align__(256) char smem[2 * ESTAGE_B];   // 40 KB
    const uint32_t sbase = smem_u32(smem);
    const int tid = threadIdx.x, lane = tid & 31, wid = tid >> 5;
    const int b = blockIdx.y;

    int bi = 0, t = blockIdx.x, rowlen = 8;
    while (t >= rowlen) { t -= rowlen; bi++; rowlen--; }
    const int bj = bi + t;
    const int m0 = bi * 64, n0 = bj * 64;

    const __half* qh = g_qh + (size_t)b * CCH * NPIX;
    const __half* ql = g_ql + (size_t)b * CCH * NPIX;

    const int wm = (wid >> 1) * 32, wn = (wid & 1) * 32;
    const int qm = lane >> 2, qp = lane & 3;

    float acc[2][4][4];
#pragma unroll
    for (int i = 0; i < 2; i++)
#pragma unroll
        for (int j = 0; j < 4; j++)
#pragma unroll
            for (int k = 0; k < 4; k++) acc[i][j][k] = 0.f;

    // per-thread copy slots: per tile 256 16B-chunks (64 rows x 4), 2 per thread
    const int cr0 = tid >> 2, cv0 = tid & 3;           // chunk 0: row, 16B-group
    const int cr1 = (tid + 128) >> 2, cv1 = tid & 3;   // chunk 1

    // ldmatrix lane addressing
    const int aro = lane & 15, akq = (lane >> 4) * 16;                 // A rows/k-half
    const int bro = (lane & 7) + 8 * (lane >> 4);                      // B rows
    const int bkq = ((lane >> 3) & 1) * 16;                            // B k-half

#define E_ISSUE(S, K0)                                                           \
    {                                                                            \
        const uint32_t tb = sbase + (S) * ESTAGE_B;                              \
        const __half* sA0 = qh + (size_t)(m0 + cr0) * NPIX + (K0);               \
        const __half* sA1 = qh + (size_t)(m0 + cr1) * NPIX + (K0);               \
        cp16(tb + cr0 * ERS_B + cv0 * 16, sA0 + cv0 * 8);                        \
        cp16(tb + cr1 * ERS_B + cv1 * 16, sA1 + cv1 * 8);                        \
        const __half* lA0 = ql + (size_t)(m0 + cr0) * NPIX + (K0);               \
        const __half* lA1 = ql + (size_t)(m0 + cr1) * NPIX + (K0);               \
        cp16(tb + ETILE_B + cr0 * ERS_B + cv0 * 16, lA0 + cv0 * 8);              \
        cp16(tb + ETILE_B + cr1 * ERS_B + cv1 * 16, lA1 + cv1 * 8);              \
        const __half* sB0 = qh + (size_t)(n0 + cr0) * NPIX + (K0);               \
        const __half* sB1 = qh + (size_t)(n0 + cr1) * NPIX + (K0);               \
        cp16(tb + 2 * ETILE_B + cr0 * ERS_B + cv0 * 16, sB0 + cv0 * 8);          \
        cp16(tb + 2 * ETILE_B + cr1 * ERS_B + cv1 * 16, sB1 + cv1 * 8);          \
        const __half* lB0 = ql + (size_t)(n0 + cr0) * NPIX + (K0);               \
        const __half* lB1 = ql + (size_t)(n0 + cr1) * NPIX + (K0);               \
        cp16(tb + 3 * ETILE_B + cr0 * ERS_B + cv0 * 16, lB0 + cv0 * 8);          \
        cp16(tb + 3 * ETILE_B + cr1 * ERS_B + cv1 * 16, lB1 + cv1 * 8);          \
        CP_COMMIT();                                                             \
    }

    E_ISSUE(0, 0);
    int s = 0;
    constexpr int NCH = NPIX / 32;   // 128
    for (int it = 0; it < NCH; ++it) {
        if (it + 1 < NCH) { E_ISSUE(s ^ 1, (it + 1) * 32); CP_WAIT(1); }
        else              { CP_WAIT(0); }
        __syncthreads();
        const uint32_t AH = sbase + s * ESTAGE_B;
        const uint32_t BH = AH + 2 * ETILE_B;
#pragma unroll
        for (int sl = 0; sl < 2; sl++) {
            uint32_t ah[2][4], al[2][4], bh[2][4], bl[2][4];
#pragma unroll
            for (int i = 0; i < 2; i++) {
                uint32_t ad = AH + (wm + i * 16 + aro) * ERS_B + sl * 32 + akq;
                ldm_x4(ah[i], ad);
                ldm_x4(al[i], ad + ETILE_B);
            }
#pragma unroll
            for (int jj = 0; jj < 2; jj++) {
                uint32_t bd = BH + (wn + jj * 16 + bro) * ERS_B + sl * 32 + bkq;
                ldm_x4(bh[jj], bd);
                ldm_x4(bl[jj], bd + ETILE_B);
            }
#pragma unroll
            for (int i = 0; i < 2; i++)
#pragma unroll
                for (int jj = 0; jj < 2; jj++) {
                    mma16(acc[i][2 * jj],     ah[i], bh[jj]);
                    mma16(acc[i][2 * jj + 1], ah[i], bh[jj] + 2);
                }
#pragma unroll
            for (int i = 0; i < 2; i++)
#pragma unroll
                for (int jj = 0; jj < 2; jj++) {
                    mma16(acc[i][2 * jj],     ah[i], bl[jj]);
                    mma16(acc[i][2 * jj + 1], ah[i], bl[jj] + 2);
                }
#pragma unroll
            for (int i = 0; i < 2; i++)
#pragma unroll
                for (int jj = 0; jj < 2; jj++) {
                    mma16(acc[i][2 * jj],     al[i], bh[jj]);
                    mma16(acc[i][2 * jj + 1], al[i], bh[jj] + 2);
                }
        }
        __syncthreads();
        s ^= 1;
    }

    float* E = g_energy + (size_t)b * CCH * CCH;
    const bool mir = (bi != bj);
#pragma unroll
    for (int i = 0; i < 2; i++)
#pragma unroll
        for (int j = 0; j < 4; j++) {
            const int m = m0 + wm + i * 16 + qm;
            const int n = n0 + wn + j * 8 + qp * 2;
            float2 v0 = make_float2(acc[i][j][0], acc[i][j][1]);
            float2 v1 = make_float2(acc[i][j][2], acc[i][j][3]);
            *(float2*)&E[(size_t)m * CCH + n]       = v0;
            *(float2*)&E[(size_t)(m + 8) * CCH + n] = v1;
            if (mir) {
                E[(size_t)n * CCH + m]           = v0.x;
                E[(size_t)(n + 1) * CCH + m]     = v0.y;
                E[(size_t)n * CCH + m + 8]       = v1.x;
                E[(size_t)(n + 1) * CCH + m + 8] = v1.y;
            }
        }
}

// ---------------------------------------------------------------------------
// Kernel 2: softmax of exp(rowmin - e)/sum, write fp16 attention
// ---------------------------------------------------------------------------
__global__ __launch_bounds__(256) void softmax_kernel()
{
    const int row  = blockIdx.x * 8 + (threadIdx.x >> 5);
    const int lane = threadIdx.x & 31;
    const float* e = g_energy + (size_t)row * CCH;
    __half* a = g_attn + (size_t)row * CCH;

    float v[16];
    float mn = 3.4e38f;
#pragma unroll
    for (int i = 0; i < 16; i++) { v[i] = e[lane + i * 32]; mn = fminf(mn, v[i]); }
#pragma unroll
    for (int o = 16; o > 0; o >>= 1)
        mn = fminf(mn, __shfl_xor_sync(0xffffffffu, mn, o));
    float s = 0.f;
#pragma unroll
    for (int i = 0; i < 16; i++) { v[i] = expf(mn - v[i]); s += v[i]; }
#pragma unroll
    for (int o = 16; o > 0; o >>= 1)
        s += __shfl_xor_sync(0xffffffffu, s, o);
    const float r = 1.0f / s;
#pragma unroll
    for (int i = 0; i < 16; i++) a[lane + i * 32] = __float2half_rn(v[i] * r);
}

// ---------------------------------------------------------------------------
// Kernel 3: y[b] = gamma * (attn[b] @ q[b]) + x[b]   (fp16 1-pass)
// A = g_attn [128 m x 32 k] row-major (stride 40 fp16); B = qh [32 k x 128 n]
// k-major (stride 136 fp16, ldmatrix.trans). 512 thr, warps 4x4, warp 32x32.
// ---------------------------------------------------------------------------
#define OA_RS_B 80
#define OA_TILE_B (128 * OA_RS_B)        // 10240 B
#define OB_RS_B  272                     // 136 fp16
#define OB_TILE_B (32 * OB_RS_B)         // 8704 B
#define OSTAGE_B (OA_TILE_B + OB_TILE_B) // 18944 B

__global__ __launch_bounds__(512) void out_kernel(const float* __restrict__ x,
                                                  const float* __restrict__ gamma,
                                                  float* __restrict__ out)
{
    __shared__ __align__(256) char smem[2 * OSTAGE_B];   // 37888 B
    const uint32_t sbase = smem_u32(smem);
    const int tid = threadIdx.x, lane = tid & 31, wid = tid >> 5;
    const int b = blockIdx.z;
    const __half* A = g_attn + (size_t)b * CCH * CCH;
    const __half* qh = g_qh + (size_t)b * CCH * NPIX;
    const int m0 = blockIdx.y * 128;
    const int n0 = blockIdx.x * 128;

    const int wm = (wid >> 2) * 32, wn = (wid & 3) * 32;
    const int qm = lane >> 2, qp = lane & 3;

    // copy slots: A 128 rows x 4 chunks = 512 (1/thread); B 32 rows x 16 = 512
    const int acr = tid >> 2, acv = tid & 3;
    const int bcr = tid >> 4, bcv = tid & 15;

    const int aro = lane & 15, akq = (lane >> 4) * 16;
    const int bro = (lane & 7) + 8 * ((lane >> 3) & 1);
    const int bco = 8 * (lane >> 4);

    float acc[2][4][4];
#pragma unroll
    for (int i = 0; i < 2; i++)
#pragma unroll
        for (int j = 0; j < 4; j++)
#pragma unroll
            for (int k = 0; k < 4; k++) acc[i][j][k] = 0.f;

#define O_ISSUE(S, K0)                                                            \
    {                                                                             \
        const uint32_t tb = sbase + (S) * OSTAGE_B;                               \
        cp16(tb + acr * OA_RS_B + acv * 16,                                       \
             A + (size_t)(m0 + acr) * CCH + (K0) + acv * 8);                      \
        cp16(tb + OA_TILE_B + bcr * OB_RS_B + bcv * 16,                           \
             qh + (size_t)((K0) + bcr) * NPIX + n0 + bcv * 8);                    \
        CP_COMMIT();                                                              \
    }

    O_ISSUE(0, 0);
    int s = 0;
    constexpr int NCH = CCH / 32;   // 16
    for (int it = 0; it < NCH; ++it) {
        if (it + 1 < NCH) { O_ISSUE(s ^ 1, (it + 1) * 32); CP_WAIT(1); }
        else              { CP_WAIT(0); }
        __syncthreads();
        const uint32_t AB = sbase + s * OSTAGE_B;
        const uint32_t BB = AB + OA_TILE_B;
#pragma unroll
        for (int sl = 0; sl < 2; sl++) {
            uint32_t af[2][4], bf[2][4];
#pragma unroll
            for (int i = 0; i < 2; i++)
                ldm_x4(af[i], AB + (wm + i * 16 + aro) * OA_RS_B + sl * 32 + akq);
#pragma unroll
            for (int jj = 0; jj < 2; jj++)
                ldm_x4_t(bf[jj], BB + (sl * 16 + bro) * OB_RS_B
                                    + (wn + jj * 16 + bco) * 2);
#pragma unroll
            for (int i = 0; i < 2; i++)
#pragma unroll
                for (int jj = 0; jj < 2; jj++) {
                    mma16(acc[i][2 * jj],     af[i], bf[jj]);
                    mma16(acc[i][2 * jj + 1], af[i], bf[jj] + 2);
                }
        }
        __syncthreads();
        s ^= 1;
    }

    const float g = *gamma;
#pragma unroll
    for (int i = 0; i < 2; i++)
#pragma unroll
        for (int j = 0; j < 4; j++) {
            const int m = m0 + wm + i * 16 + qm;
            const int n = n0 + wn + j * 8 + qp * 2;
            {
                const size_t p = (size_t)(b * CCH + m) * NPIX + n;
                float2 xv = *(const float2*)(x + p);
                float2 o;
                o.x = fmaf(g, acc[i][j][0], xv.x);
                o.y = fmaf(g, acc[i][j][1], xv.y);
                *(float2*)(out + p) = o;
            }
            {
                const size_t p = (size_t)(b * CCH + m + 8) * NPIX + n;
                float2 xv = *(const float2*)(x + p);
                float2 o;
                o.x = fmaf(g, acc[i][j][2], xv.x);
                o.y = fmaf(g, acc[i][j][3], xv.y);
                *(float2*)(out + p) = o;
            }
        }
}

// ---------------------------------------------------------------------------
extern "C" void kernel_launch(void* const* d_in, const int* in_sizes, int n_in,
                              void* d_out, int out_size)
{
    const float* x     = (const float*)d_in[0];
    const float* gamma = (const float*)d_in[1];
    float* out = (float*)d_out;

    split_kernel<<<(unsigned)(NTOT / 4 / 256), 256>>>(x);
    energy_kernel<<<dim3(36, BATCH), 128>>>();
    softmax_kernel<<<(BATCH * CCH) / 8, 256>>>();
    out_kernel<<<dim3(NPIX / 128, CCH / 128, BATCH), 512>>>(x, gamma, out);
}